// round 9
// baseline (speedup 1.0000x reference)
#include <cuda_runtime.h>
#include <cuda_bf16.h>

// GHM-C loss, fused single kernel (R9 = R8 with the magic-floor constant-folding
// bug fixed: -0.5 must be applied at small magnitude BEFORE adding 1.5*2^23).
//   t in {0,1} exact. nz2 = -z*log2e = x*(2t-1)*log2e
//   u = 2^{nz2}; w = 1+u; g = sigmoid(z) = 1/w; softplus(z)/ln2 = log2(w) - nz2
//   result = sum_b (ln2 * S_b) / max(cnt_b * nonempty, 1e-4)

#define BINS      10
#define NTHREADS  256
#define NBLOCKS   740          // 148 SMs * 5 resident blocks (40KB smem) -> 1 wave
#define LOG2E_F   1.4426950408889634f
#define LN2_D     0.6931471805599453
#define MAGIC_F   12582912.0f  // 1.5 * 2^23
#define REP_BYTES (BINS * NTHREADS * 8)

__device__ double        g_cnt[BINS];   // zero-initialized at module load
__device__ double        g_sum[BINS];
__device__ unsigned int  g_done;

__device__ __forceinline__ float ex2f(float x) { float y; asm("ex2.approx.f32 %0, %1;" : "=f"(y) : "f"(x)); return y; }
__device__ __forceinline__ float lg2f(float x) { float y; asm("lg2.approx.f32 %0, %1;" : "=f"(y) : "f"(x)); return y; }
__device__ __forceinline__ float rcpf(float x) { float y; asm("rcp.approx.f32 %0, %1;" : "=f"(y) : "f"(x)); return y; }

// compute (smem byte offset within a replica, p) for one element
__device__ __forceinline__ void ghm_calc(float xk, float tk, int& off, float& p)
{
    float s   = fmaf(tk, 2.0f * LOG2E_F, -LOG2E_F);  // (2t-1)*log2e
    float nz2 = xk * s;                              // -z*log2e
    float u   = ex2f(nz2);                           // MUFU.EX2
    float w   = 1.0f + u;
    float r   = rcpf(w);                             // g = sigmoid(z), MUFU.RCP
    // magic floor: q-0.5 computed at small magnitude FIRST (representable),
    // then +1.5*2^23 rounds-to-nearest -> floor(q). q < 10 => bin <= 9.
    float m   = fmaf(r, 9.9999f, -0.5f) + MAGIC_F;
    off       = (__float_as_int(m) & 0xF) << 11;     // bin * NTHREADS * 8
    p         = lg2f(w) - nz2;                       // softplus(z)/ln2, MUFU.LG2
}

__device__ __forceinline__ void ghm_rmw(char* base, int off, float p)
{
    float2* slot = (float2*)(base + off);
    float2 h = *slot;
    h.x += 1.0f;
    h.y += p;
    *slot = h;
}

__global__ __launch_bounds__(NTHREADS, 5)
void ghm_fused_kernel(const float4* __restrict__ xv4,
                      const float4* __restrict__ tv4,
                      int nvec, int n,
                      float* __restrict__ out)
{
    // two full private-histogram replicas -> two independent RMW chains
    __shared__ float2 hist[2 * BINS * NTHREADS];
    __shared__ bool   s_last;

    const int tid = threadIdx.x;
    #pragma unroll
    for (int b = 0; b < 2 * BINS; ++b)
        hist[b * NTHREADS + tid] = make_float2(0.0f, 0.0f);
    __syncthreads();

    char* base0 = (char*)&hist[tid];
    char* base1 = base0 + REP_BYTES;
    const int stride  = gridDim.x * NTHREADS;
    const int stride2 = stride * 2;

    int i = blockIdx.x * NTHREADS + tid;
    for (; i + stride < nvec; i += stride2) {
        float4 xa = __ldcs(&xv4[i]);
        float4 ta = __ldcs(&tv4[i]);
        float4 xb = __ldcs(&xv4[i + stride]);
        float4 tb = __ldcs(&tv4[i + stride]);

        int   o0, o1, o2, o3, o4, o5, o6, o7;
        float p0, p1, p2, p3, p4, p5, p6, p7;
        ghm_calc(xa.x, ta.x, o0, p0);
        ghm_calc(xa.y, ta.y, o1, p1);
        ghm_calc(xa.z, ta.z, o2, p2);
        ghm_calc(xa.w, ta.w, o3, p3);
        ghm_calc(xb.x, tb.x, o4, p4);
        ghm_calc(xb.y, tb.y, o5, p5);
        ghm_calc(xb.z, tb.z, o6, p6);
        ghm_calc(xb.w, tb.w, o7, p7);
        // two independent 4-deep RMW chains
        ghm_rmw(base0, o0, p0);  ghm_rmw(base1, o1, p1);
        ghm_rmw(base0, o2, p2);  ghm_rmw(base1, o3, p3);
        ghm_rmw(base0, o4, p4);  ghm_rmw(base1, o5, p5);
        ghm_rmw(base0, o6, p6);  ghm_rmw(base1, o7, p7);
    }
    if (i < nvec) {
        float4 xa = __ldcs(&xv4[i]);
        float4 ta = __ldcs(&tv4[i]);
        int   o0, o1, o2, o3;
        float p0, p1, p2, p3;
        ghm_calc(xa.x, ta.x, o0, p0);
        ghm_calc(xa.y, ta.y, o1, p1);
        ghm_calc(xa.z, ta.z, o2, p2);
        ghm_calc(xa.w, ta.w, o3, p3);
        ghm_rmw(base0, o0, p0);  ghm_rmw(base1, o1, p1);
        ghm_rmw(base0, o2, p2);  ghm_rmw(base1, o3, p3);
    }

    // scalar tail (n not multiple of 4) -- block 0 only
    if (blockIdx.x == 0) {
        int basei = nvec * 4;
        if (basei + tid < n) {
            const float* xf = (const float*)xv4;
            const float* tf = (const float*)tv4;
            int o; float p;
            ghm_calc(xf[basei + tid], tf[basei + tid], o, p);
            ghm_rmw(base0, o, p);
        }
    }
    __syncthreads();

    // fold replica 1 into replica 0
    #pragma unroll
    for (int b = 0; b < BINS; ++b) {
        float2 a = hist[b * NTHREADS + tid];
        float2 c = hist[(BINS + b) * NTHREADS + tid];
        a.x += c.x;
        a.y += c.y;
        hist[b * NTHREADS + tid] = a;
    }
    __syncthreads();

    // tree-reduce the 256 private histograms
    for (int sred = NTHREADS / 2; sred > 0; sred >>= 1) {
        if (tid < sred) {
            #pragma unroll
            for (int b = 0; b < BINS; ++b) {
                float2 a = hist[b * NTHREADS + tid];
                float2 c = hist[b * NTHREADS + tid + sred];
                a.x += c.x;
                a.y += c.y;
                hist[b * NTHREADS + tid] = a;
            }
        }
        __syncthreads();
    }

    if (tid < BINS) {
        atomicAdd(&g_cnt[tid], (double)hist[tid * NTHREADS].x);
        atomicAdd(&g_sum[tid], (double)hist[tid * NTHREADS].y);
    }

    // last-block-done protocol
    __threadfence();
    if (tid == 0) {
        unsigned int prev = atomicAdd(&g_done, 1u);
        s_last = (prev == (unsigned int)(gridDim.x - 1));
    }
    __syncthreads();

    if (s_last && tid == 0) {
        __threadfence();   // acquire: make all blocks' atomics visible
        volatile double* vc = (volatile double*)g_cnt;
        volatile double* vs = (volatile double*)g_sum;
        double cnt[BINS], sum[BINS];
        double ne = 0.0;
        #pragma unroll
        for (int b = 0; b < BINS; ++b) {
            cnt[b] = vc[b];
            sum[b] = vs[b];
            if (cnt[b] > 0.0) ne += 1.0;
        }
        double res = 0.0;
        #pragma unroll
        for (int b = 0; b < BINS; ++b) {
            double gd = cnt[b] * ne;
            if (gd < 1e-4) gd = 1e-4;
            res += (sum[b] * LN2_D) / gd;
        }
        out[0] = (float)res;

        // reset for the next graph replay (deterministic re-execution)
        #pragma unroll
        for (int b = 0; b < BINS; ++b) { g_cnt[b] = 0.0; g_sum[b] = 0.0; }
        __threadfence();
        g_done = 0u;
    }
}

extern "C" void kernel_launch(void* const* d_in, const int* in_sizes, int n_in,
                              void* d_out, int out_size) {
    const float* x = (const float*)d_in[0];
    const float* t = (const float*)d_in[1];
    int n    = in_sizes[0];
    int nvec = n >> 2;

    ghm_fused_kernel<<<NBLOCKS, NTHREADS>>>((const float4*)x, (const float4*)t,
                                            nvec, n, (float*)d_out);
}

// round 10
// speedup vs baseline: 1.1612x; 1.1612x over previous
#include <cuda_runtime.h>
#include <cuda_bf16.h>

// GHM-C loss, fused single kernel.
// R10 = R7 structure (single private histogram, interleaved calc+RMW, 2x unroll,
// max occupancy) + R9 math (pure-MUFU via PTX approx ops, fixed magic floor).
//   t in {0,1} exact. nz2 = -z*log2e = x*(2t-1)*log2e
//   u = 2^{nz2}; w = 1+u; g = sigmoid(z) = 1/w; softplus(z)/ln2 = log2(w) - nz2
//   result = sum_b (ln2 * S_b) / max(cnt_b * nonempty, 1e-4)

#define BINS      10
#define NTHREADS  256
#define NBLOCKS   1184         // 148 SMs * 8 resident blocks -> 1 wave
#define LOG2E_F   1.4426950408889634f
#define LN2_D     0.6931471805599453
#define MAGIC_F   12582912.0f  // 1.5 * 2^23

__device__ double        g_cnt[BINS];   // zero-initialized at module load
__device__ double        g_sum[BINS];
__device__ unsigned int  g_done;

__device__ __forceinline__ float ex2f(float x) { float y; asm("ex2.approx.f32 %0, %1;" : "=f"(y) : "f"(x)); return y; }
__device__ __forceinline__ float lg2f(float x) { float y; asm("lg2.approx.f32 %0, %1;" : "=f"(y) : "f"(x)); return y; }
__device__ __forceinline__ float rcpf(float x) { float y; asm("rcp.approx.f32 %0, %1;" : "=f"(y) : "f"(x)); return y; }

__device__ __forceinline__ void ghm_elem(float xk, float tk, char* hist_base)
{
    float s   = fmaf(tk, 2.0f * LOG2E_F, -LOG2E_F);  // (2t-1)*log2e
    float nz2 = xk * s;                              // -z*log2e
    float u   = ex2f(nz2);                           // MUFU.EX2
    float w   = 1.0f + u;
    float r   = rcpf(w);                             // g = sigmoid(z), MUFU.RCP
    // magic floor: q-0.5 at small magnitude FIRST (representable), then
    // +1.5*2^23 rounds-to-nearest -> floor(q). q < 10 => bin <= 9.
    float m   = fmaf(r, 9.9999f, -0.5f) + MAGIC_F;
    int   off = (__float_as_int(m) & 0xF) << 11;     // bin * NTHREADS * 8
    float p   = lg2f(w) - nz2;                       // softplus(z)/ln2, MUFU.LG2

    float2* slot = (float2*)(hist_base + off);
    float2 h = *slot;
    h.x += 1.0f;
    h.y += p;
    *slot = h;
}

__global__ __launch_bounds__(NTHREADS, 8)
void ghm_fused_kernel(const float4* __restrict__ xv4,
                      const float4* __restrict__ tv4,
                      int nvec, int n,
                      float* __restrict__ out)
{
    __shared__ float2 hist[BINS * NTHREADS];   // [bin][tid] : {count, p_sum}
    __shared__ bool   s_last;

    const int tid = threadIdx.x;
    #pragma unroll
    for (int b = 0; b < BINS; ++b)
        hist[b * NTHREADS + tid] = make_float2(0.0f, 0.0f);
    __syncthreads();

    char* hist_base = (char*)&hist[tid];
    const int stride  = gridDim.x * NTHREADS;
    const int stride2 = stride * 2;

    int i = blockIdx.x * NTHREADS + tid;
    for (; i + stride < nvec; i += stride2) {
        float4 xa = __ldcs(&xv4[i]);
        float4 ta = __ldcs(&tv4[i]);
        float4 xb = __ldcs(&xv4[i + stride]);
        float4 tb = __ldcs(&tv4[i + stride]);
        ghm_elem(xa.x, ta.x, hist_base);
        ghm_elem(xa.y, ta.y, hist_base);
        ghm_elem(xa.z, ta.z, hist_base);
        ghm_elem(xa.w, ta.w, hist_base);
        ghm_elem(xb.x, tb.x, hist_base);
        ghm_elem(xb.y, tb.y, hist_base);
        ghm_elem(xb.z, tb.z, hist_base);
        ghm_elem(xb.w, tb.w, hist_base);
    }
    if (i < nvec) {
        float4 xa = __ldcs(&xv4[i]);
        float4 ta = __ldcs(&tv4[i]);
        ghm_elem(xa.x, ta.x, hist_base);
        ghm_elem(xa.y, ta.y, hist_base);
        ghm_elem(xa.z, ta.z, hist_base);
        ghm_elem(xa.w, ta.w, hist_base);
    }

    // scalar tail (n not multiple of 4) -- block 0 only
    if (blockIdx.x == 0) {
        int basei = nvec * 4;
        if (basei + tid < n) {
            const float* xf = (const float*)xv4;
            const float* tf = (const float*)tv4;
            ghm_elem(xf[basei + tid], tf[basei + tid], hist_base);
        }
    }
    __syncthreads();

    // tree-reduce the 256 private histograms
    for (int sred = NTHREADS / 2; sred > 0; sred >>= 1) {
        if (tid < sred) {
            #pragma unroll
            for (int b = 0; b < BINS; ++b) {
                float2 a = hist[b * NTHREADS + tid];
                float2 c = hist[b * NTHREADS + tid + sred];
                a.x += c.x;
                a.y += c.y;
                hist[b * NTHREADS + tid] = a;
            }
        }
        __syncthreads();
    }

    if (tid < BINS) {
        atomicAdd(&g_cnt[tid], (double)hist[tid * NTHREADS].x);
        atomicAdd(&g_sum[tid], (double)hist[tid * NTHREADS].y);
    }

    // last-block-done protocol
    __threadfence();
    if (tid == 0) {
        unsigned int prev = atomicAdd(&g_done, 1u);
        s_last = (prev == (unsigned int)(gridDim.x - 1));
    }
    __syncthreads();

    if (s_last && tid == 0) {
        __threadfence();   // acquire: make all blocks' atomics visible
        volatile double* vc = (volatile double*)g_cnt;
        volatile double* vs = (volatile double*)g_sum;
        double cnt[BINS], sum[BINS];
        double ne = 0.0;
        #pragma unroll
        for (int b = 0; b < BINS; ++b) {
            cnt[b] = vc[b];
            sum[b] = vs[b];
            if (cnt[b] > 0.0) ne += 1.0;
        }
        double res = 0.0;
        #pragma unroll
        for (int b = 0; b < BINS; ++b) {
            double gd = cnt[b] * ne;
            if (gd < 1e-4) gd = 1e-4;
            res += (sum[b] * LN2_D) / gd;
        }
        out[0] = (float)res;

        // reset for the next graph replay (deterministic re-execution)
        #pragma unroll
        for (int b = 0; b < BINS; ++b) { g_cnt[b] = 0.0; g_sum[b] = 0.0; }
        __threadfence();
        g_done = 0u;
    }
}

extern "C" void kernel_launch(void* const* d_in, const int* in_sizes, int n_in,
                              void* d_out, int out_size) {
    const float* x = (const float*)d_in[0];
    const float* t = (const float*)d_in[1];
    int n    = in_sizes[0];
    int nvec = n >> 2;

    ghm_fused_kernel<<<NBLOCKS, NTHREADS>>>((const float4*)x, (const float4*)t,
                                            nvec, n, (float*)d_out);
}